// round 11
// baseline (speedup 1.0000x reference)
#include <cuda_runtime.h>
#include <cstdint>

#define BATCH 64
#define FEAT  784
#define DIM   1001
#define DIMSQ (DIM * DIM)        // 1002001; DIM % 8 == 1, DIMSQ % 8 == 1
#define ROWS_PER_CTA 14
#define CTAS_X 72                // 72*14 = 1008 >= 1001

// 256-bit streaming store (sm_100+): 8 x b32, 32B-aligned, evict-first (.cs).
#define STG256_CS(p, a0,a1,a2,a3,a4,a5,a6,a7)                                  \
    asm volatile("st.global.cs.v8.b32 [%0], {%1,%2,%3,%4,%5,%6,%7,%8};"        \
                 :: "l"(p),                                                    \
                    "r"(__float_as_uint(a0)), "r"(__float_as_uint(a1)),        \
                    "r"(__float_as_uint(a2)), "r"(__float_as_uint(a3)),        \
                    "r"(__float_as_uint(a4)), "r"(__float_as_uint(a5)),        \
                    "r"(__float_as_uint(a6)), "r"(__float_as_uint(a7))         \
                 : "memory")

// Row-start element offset o = b*DIMSQ + i*DIM  ->  o mod 8 == (b + i) & 7.
// 32B-aligned octets start at j == A8 (mod 8), A8 = (-(b+i)) & 7.
// NQ(A8) = 125 for A8<=1 else 124 (octets never overrun the row).
// Tail [A8+8*NQ, 1001) always starts at j >= 994 > FEAT -> exactly 0.
__global__ void __launch_bounds__(128) amp_kernel(const float* __restrict__ x,
                                                  float* __restrict__ out) {
    __shared__ float s_sm[1032];           // scaled state, zero-padded past FEAT
    __shared__ float red[4];
    __shared__ float s_inv;

    const int tid = threadIdx.x;
    const int b   = blockIdx.y;
    const float* xb = x + b * FEAT;                            // 16B-aligned
    const float4* xb4 = reinterpret_cast<const float4*>(xb);   // 196 float4s
    float4* s_sm4 = reinterpret_cast<float4*>(s_sm);           // 258 float4s

    // ---- vectorized norm ----
    float4 v0 = xb4[tid];                                      // tid < 128 < 196
    float4 v1 = make_float4(0.f, 0.f, 0.f, 0.f);
    if (tid < 68) v1 = xb4[tid + 128];
    float p = v0.x * v0.x + v0.y * v0.y + v0.z * v0.z + v0.w * v0.w
            + v1.x * v1.x + v1.y * v1.y + v1.z * v1.z + v1.w * v1.w;
    #pragma unroll
    for (int o = 16; o > 0; o >>= 1) p += __shfl_xor_sync(0xFFFFFFFFu, p, o);
    if ((tid & 31) == 0) red[tid >> 5] = p;
    __syncthreads();
    if (tid == 0) s_inv = rsqrtf(red[0] + red[1] + red[2] + red[3]);
    __syncthreads();
    const float inv = s_inv;

    {
        s_sm4[tid] = make_float4(v0.x * inv, v0.y * inv, v0.z * inv, v0.w * inv);
        if (tid < 68)
            s_sm4[tid + 128] = make_float4(v1.x * inv, v1.y * inv, v1.z * inv, v1.w * inv);
        if (tid >= 68 && tid < 130)                            // float4 idx 196..257
            s_sm4[tid + 128] = make_float4(0.f, 0.f, 0.f, 0.f);
    }
    __syncthreads();

    // ---- register window: w[0..15] = s[8t .. 8t+16) ----
    float w[16];
    #pragma unroll
    for (int q = 0; q < 4; q++) {
        const float4 a = *reinterpret_cast<const float4*>(&s_sm[8 * tid + 4 * q]);
        w[4*q+0] = a.x; w[4*q+1] = a.y; w[4*q+2] = a.z; w[4*q+3] = a.w;
    }

    const int i0   = blockIdx.x * ROWS_PER_CTA;
    const int iend = (i0 + ROWS_PER_CTA < DIM) ? (i0 + ROWS_PER_CTA) : DIM;

    for (int i = i0; i < iend; ++i) {
        const float si = s_sm[i];                              // broadcast LDS
        float* rowp    = out + (size_t)b * DIMSQ + (size_t)i * DIM;
        const int A8   = (-(b + i)) & 7;

        // head scalars j in [0, A8)
        if (tid < A8) __stcs(rowp + tid, si * s_sm[tid]);

        #define CASE(K)                                                            \
            {                                                                      \
                constexpr int NQ = ((K) <= 1) ? 125 : 124;                         \
                constexpr int TS = (K) + 8 * NQ;        /* tail start */           \
                if (tid < NQ) {                                                    \
                    float* dst = rowp + (K) + 8 * tid;  /* 32B-aligned */          \
                    STG256_CS(dst, si*w[(K)+0], si*w[(K)+1], si*w[(K)+2],          \
                                   si*w[(K)+3], si*w[(K)+4], si*w[(K)+5],          \
                                   si*w[(K)+6], si*w[(K)+7]);                      \
                }                                                                  \
                if (TS < DIM && tid >= 120 && tid < 120 + (DIM - TS))              \
                    __stcs(rowp + TS + (tid - 120), 0.0f);                         \
            }
        switch (A8) {
            case 0: CASE(0); break;
            case 1: CASE(1); break;
            case 2: CASE(2); break;
            case 3: CASE(3); break;
            case 4: CASE(4); break;
            case 5: CASE(5); break;
            case 6: CASE(6); break;
            default: CASE(7); break;
        }
        #undef CASE
    }
}

extern "C" void kernel_launch(void* const* d_in, const int* in_sizes, int n_in,
                              void* d_out, int out_size) {
    const float* x   = (const float*)d_in[0];
    float*       out = (float*)d_out;
    amp_kernel<<<dim3(CTAS_X, BATCH), 128>>>(x, out);
}

// round 12
// speedup vs baseline: 1.0089x; 1.0089x over previous
#include <cuda_runtime.h>
#include <cstdint>

#define BATCH 64
#define FEAT  784
#define DIM   1001
#define DIMSQ (DIM * DIM)        // 1002001; DIM % 8 == 1, DIMSQ % 8 == 1
#define ROWS_PER_CTA 14
#define CTAS_X 72                // 72*14 = 1008 >= 1001

// 256-bit store (sm_100+): 8 x b32, requires 32B-aligned address.
#define STG256(p, a0,a1,a2,a3,a4,a5,a6,a7)                                     \
    asm volatile("st.global.v8.b32 [%0], {%1,%2,%3,%4,%5,%6,%7,%8};"           \
                 :: "l"(p),                                                    \
                    "r"(__float_as_uint(a0)), "r"(__float_as_uint(a1)),        \
                    "r"(__float_as_uint(a2)), "r"(__float_as_uint(a3)),        \
                    "r"(__float_as_uint(a4)), "r"(__float_as_uint(a5)),        \
                    "r"(__float_as_uint(a6)), "r"(__float_as_uint(a7))         \
                 : "memory")

// Row-start element offset o = b*DIMSQ + i*DIM  ->  o mod 8 == (b + i) & 7.
// 32B-aligned octets start at j == A8 (mod 8), A8 = (-(b+i)) & 7.
// NQ(A8) = 125 for A8<=1 else 124 (octets never overrun the row).
// Tail [A8+8*NQ, 1001) always starts at j >= 994 > FEAT -> exactly 0.
__global__ void __launch_bounds__(128) amp_kernel(const float* __restrict__ x,
                                                  float* __restrict__ out) {
    __shared__ float s_sm[1032];           // scaled state, zero-padded past FEAT
    __shared__ float red[4];
    __shared__ float s_inv;

    const int tid = threadIdx.x;
    const int b   = blockIdx.y;
    const float* xb = x + b * FEAT;                            // 16B-aligned
    const float4* xb4 = reinterpret_cast<const float4*>(xb);   // 196 float4s
    float4* s_sm4 = reinterpret_cast<float4*>(s_sm);           // 258 float4s

    // ---- vectorized norm (R7/R9-proven) ----
    float4 v0 = xb4[tid];                                      // tid < 128 < 196
    float4 v1 = make_float4(0.f, 0.f, 0.f, 0.f);
    if (tid < 68) v1 = xb4[tid + 128];
    float p = v0.x * v0.x + v0.y * v0.y + v0.z * v0.z + v0.w * v0.w
            + v1.x * v1.x + v1.y * v1.y + v1.z * v1.z + v1.w * v1.w;
    #pragma unroll
    for (int o = 16; o > 0; o >>= 1) p += __shfl_xor_sync(0xFFFFFFFFu, p, o);
    if ((tid & 31) == 0) red[tid >> 5] = p;
    __syncthreads();
    if (tid == 0) s_inv = rsqrtf(red[0] + red[1] + red[2] + red[3]);
    __syncthreads();
    const float inv = s_inv;

    {
        s_sm4[tid] = make_float4(v0.x * inv, v0.y * inv, v0.z * inv, v0.w * inv);
        if (tid < 68)
            s_sm4[tid + 128] = make_float4(v1.x * inv, v1.y * inv, v1.z * inv, v1.w * inv);
        if (tid >= 68 && tid < 130)                            // float4 idx 196..257
            s_sm4[tid + 128] = make_float4(0.f, 0.f, 0.f, 0.f);
    }
    __syncthreads();

    // ---- register window: w[0..15] = s[8t .. 8t+16) ----
    float w[16];
    #pragma unroll
    for (int q = 0; q < 4; q++) {
        const float4 a = *reinterpret_cast<const float4*>(&s_sm[8 * tid + 4 * q]);
        w[4*q+0] = a.x; w[4*q+1] = a.y; w[4*q+2] = a.z; w[4*q+3] = a.w;
    }

    const int i0   = blockIdx.x * ROWS_PER_CTA;
    const int iend = (i0 + ROWS_PER_CTA < DIM) ? (i0 + ROWS_PER_CTA) : DIM;

    // Running row pointer (one 64-bit mul total) + si software prefetch.
    float* rowp = out + (size_t)b * DIMSQ + (size_t)i0 * DIM;
    float  si   = s_sm[i0];

    for (int i = i0; i < iend; ++i, rowp += DIM) {
        const float cur = si;
        if (i + 1 < iend) si = s_sm[i + 1];                    // prefetch next broadcast

        const int A8 = (-(b + i)) & 7;

        // head scalars j in [0, A8)
        if (tid < A8) rowp[tid] = cur * s_sm[tid];

        #define CASE(K)                                                            \
            {                                                                      \
                constexpr int NQ = ((K) <= 1) ? 125 : 124;                         \
                constexpr int TS = (K) + 8 * NQ;        /* tail start */           \
                if (tid < NQ) {                                                    \
                    float* dst = rowp + (K) + 8 * tid;  /* 32B-aligned */          \
                    STG256(dst, cur*w[(K)+0], cur*w[(K)+1], cur*w[(K)+2],          \
                                cur*w[(K)+3], cur*w[(K)+4], cur*w[(K)+5],          \
                                cur*w[(K)+6], cur*w[(K)+7]);                       \
                }                                                                  \
                if (TS < DIM && tid >= 120 && tid < 120 + (DIM - TS))              \
                    rowp[TS + (tid - 120)] = 0.0f;                                 \
            }
        switch (A8) {
            case 0: CASE(0); break;
            case 1: CASE(1); break;
            case 2: CASE(2); break;
            case 3: CASE(3); break;
            case 4: CASE(4); break;
            case 5: CASE(5); break;
            case 6: CASE(6); break;
            default: CASE(7); break;
        }
        #undef CASE
    }
}

extern "C" void kernel_launch(void* const* d_in, const int* in_sizes, int n_in,
                              void* d_out, int out_size) {
    const float* x   = (const float*)d_in[0];
    float*       out = (float*)d_out;
    amp_kernel<<<dim3(CTAS_X, BATCH), 128>>>(x, out);
}

// round 13
// speedup vs baseline: 1.0119x; 1.0030x over previous
#include <cuda_runtime.h>
#include <cstdint>

#define BATCH 64
#define FEAT  784
#define DIM   1001
#define DIMSQ (DIM * DIM)        // 1002001; DIM % 8 == 1, DIMSQ % 8 == 1
#define ROWS_PER_CTA 14
#define CTAS_X 72                // 72*14 = 1008 >= 1001

// 256-bit store (sm_100+): 8 x b32, requires 32B-aligned address.
#define STG256(p, a0,a1,a2,a3,a4,a5,a6,a7)                                     \
    asm volatile("st.global.v8.b32 [%0], {%1,%2,%3,%4,%5,%6,%7,%8};"           \
                 :: "l"(p),                                                    \
                    "r"(__float_as_uint(a0)), "r"(__float_as_uint(a1)),        \
                    "r"(__float_as_uint(a2)), "r"(__float_as_uint(a3)),        \
                    "r"(__float_as_uint(a4)), "r"(__float_as_uint(a5)),        \
                    "r"(__float_as_uint(a6)), "r"(__float_as_uint(a7))         \
                 : "memory")

// Row-start element offset o = b*DIMSQ + i*DIM  ->  o mod 8 == (b + i) & 7.
// 32B-aligned octets start at j == A8 (mod 8), A8 = (-(b+i)) & 7.
// Octet count NQ(A8): 125 for A8<=1, else 124 (so octets never overrun the row).
//   coverage: [A8, A8+8*NQ); head [0,A8); tail [A8+8*NQ, 1001).
// Tail always starts at j >= 994 > FEAT -> tail values are exactly 0.
__global__ void __launch_bounds__(128) amp_kernel(const float* __restrict__ x,
                                                  float* __restrict__ out) {
    __shared__ float s_sm[1032];           // scaled state, zero-padded past FEAT
    __shared__ float red[4];
    __shared__ float s_inv;

    const int tid = threadIdx.x;
    const int b   = blockIdx.y;
    const float* xb = x + b * FEAT;                            // 16B-aligned
    const float4* xb4 = reinterpret_cast<const float4*>(xb);   // 196 float4s
    float4* s_sm4 = reinterpret_cast<float4*>(s_sm);           // 258 float4s

    // ---- vectorized norm ----
    float4 v0 = xb4[tid];                                      // tid < 128 < 196
    float4 v1 = make_float4(0.f, 0.f, 0.f, 0.f);
    if (tid < 68) v1 = xb4[tid + 128];
    float p = v0.x * v0.x + v0.y * v0.y + v0.z * v0.z + v0.w * v0.w
            + v1.x * v1.x + v1.y * v1.y + v1.z * v1.z + v1.w * v1.w;
    #pragma unroll
    for (int o = 16; o > 0; o >>= 1) p += __shfl_xor_sync(0xFFFFFFFFu, p, o);
    if ((tid & 31) == 0) red[tid >> 5] = p;
    __syncthreads();
    if (tid == 0) s_inv = rsqrtf(red[0] + red[1] + red[2] + red[3]);
    __syncthreads();
    const float inv = s_inv;

    {
        s_sm4[tid] = make_float4(v0.x * inv, v0.y * inv, v0.z * inv, v0.w * inv);
        if (tid < 68)
            s_sm4[tid + 128] = make_float4(v1.x * inv, v1.y * inv, v1.z * inv, v1.w * inv);
        if (tid >= 68 && tid < 130)                            // float4 idx 196..257
            s_sm4[tid + 128] = make_float4(0.f, 0.f, 0.f, 0.f);
    }
    __syncthreads();

    // ---- register window: w[0..15] = s[8t .. 8t+16) ----
    float w[16];
    #pragma unroll
    for (int q = 0; q < 4; q++) {
        const float4 a = *reinterpret_cast<const float4*>(&s_sm[8 * tid + 4 * q]);
        w[4*q+0] = a.x; w[4*q+1] = a.y; w[4*q+2] = a.z; w[4*q+3] = a.w;
    }

    const int i0   = blockIdx.x * ROWS_PER_CTA;
    const int iend = (i0 + ROWS_PER_CTA < DIM) ? (i0 + ROWS_PER_CTA) : DIM;

    for (int i = i0; i < iend; ++i) {
        const float si = s_sm[i];                              // broadcast LDS
        float* rowp    = out + (size_t)b * DIMSQ + (size_t)i * DIM;
        const int A8   = (-(b + i)) & 7;

        // head scalars j in [0, A8)
        if (tid < A8) rowp[tid] = si * s_sm[tid];

        // per-phase: NQ octets + zero tail (tail j >= 994 > FEAT)
        #define CASE(K)                                                            \
            {                                                                      \
                constexpr int NQ = ((K) <= 1) ? 125 : 124;                         \
                constexpr int TS = (K) + 8 * NQ;        /* tail start */           \
                if (tid < NQ) {                                                    \
                    float* dst = rowp + (K) + 8 * tid;  /* 32B-aligned */          \
                    STG256(dst, si*w[(K)+0], si*w[(K)+1], si*w[(K)+2],             \
                                si*w[(K)+3], si*w[(K)+4], si*w[(K)+5],             \
                                si*w[(K)+6], si*w[(K)+7]);                         \
                }                                                                  \
                if (TS < DIM && tid >= 120 && tid < 120 + (DIM - TS))              \
                    rowp[TS + (tid - 120)] = 0.0f;                                 \
            }
        switch (A8) {
            case 0: CASE(0); break;
            case 1: CASE(1); break;
            case 2: CASE(2); break;
            case 3: CASE(3); break;
            case 4: CASE(4); break;
            case 5: CASE(5); break;
            case 6: CASE(6); break;
            default: CASE(7); break;
        }
        #undef CASE
    }
}

extern "C" void kernel_launch(void* const* d_in, const int* in_sizes, int n_in,
                              void* d_out, int out_size) {
    const float* x   = (const float*)d_in[0];
    float*       out = (float*)d_out;
    amp_kernel<<<dim3(CTAS_X, BATCH), 128>>>(x, out);
}

// round 14
// speedup vs baseline: 1.0592x; 1.0468x over previous
#include <cuda_runtime.h>
#include <cstdint>

#define BATCH 64
#define FEAT  784
#define DIM   1001
#define DIMSQ (DIM * DIM)        // 1002001; DIM % 8 == 1, DIMSQ % 8 == 1
#define ROWS_PER_CTA 7
#define CTAS_X 143               // 143*7 = 1001 exactly: no clamp, uniform CTAs

// 256-bit store (sm_100+): 8 x b32, requires 32B-aligned address.
#define STG256(p, a0,a1,a2,a3,a4,a5,a6,a7)                                     \
    asm volatile("st.global.v8.b32 [%0], {%1,%2,%3,%4,%5,%6,%7,%8};"           \
                 :: "l"(p),                                                    \
                    "r"(__float_as_uint(a0)), "r"(__float_as_uint(a1)),        \
                    "r"(__float_as_uint(a2)), "r"(__float_as_uint(a3)),        \
                    "r"(__float_as_uint(a4)), "r"(__float_as_uint(a5)),        \
                    "r"(__float_as_uint(a6)), "r"(__float_as_uint(a7))         \
                 : "memory")

// Row-start element offset o = b*DIMSQ + i*DIM  ->  o mod 8 == (b + i) & 7.
// 32B-aligned octets start at j == A8 (mod 8), A8 = (-(b+i)) & 7.
// Octet count NQ(A8): 125 for A8<=1, else 124 (octets never overrun the row).
//   coverage: [A8, A8+8*NQ); head [0,A8); tail [A8+8*NQ, 1001).
// Tail always starts at j >= 994 > FEAT -> tail values are exactly 0.
__global__ void __launch_bounds__(128) amp_kernel(const float* __restrict__ x,
                                                  float* __restrict__ out) {
    __shared__ float s_sm[1032];           // scaled state, zero-padded past FEAT
    __shared__ float red[4];
    __shared__ float s_inv;

    const int tid = threadIdx.x;
    const int b   = blockIdx.y;
    const float* xb = x + b * FEAT;                            // 16B-aligned
    const float4* xb4 = reinterpret_cast<const float4*>(xb);   // 196 float4s
    float4* s_sm4 = reinterpret_cast<float4*>(s_sm);           // 258 float4s

    // ---- vectorized norm ----
    float4 v0 = xb4[tid];                                      // tid < 128 < 196
    float4 v1 = make_float4(0.f, 0.f, 0.f, 0.f);
    if (tid < 68) v1 = xb4[tid + 128];
    float p = v0.x * v0.x + v0.y * v0.y + v0.z * v0.z + v0.w * v0.w
            + v1.x * v1.x + v1.y * v1.y + v1.z * v1.z + v1.w * v1.w;
    #pragma unroll
    for (int o = 16; o > 0; o >>= 1) p += __shfl_xor_sync(0xFFFFFFFFu, p, o);
    if ((tid & 31) == 0) red[tid >> 5] = p;
    __syncthreads();
    if (tid == 0) s_inv = rsqrtf(red[0] + red[1] + red[2] + red[3]);
    __syncthreads();
    const float inv = s_inv;

    {
        s_sm4[tid] = make_float4(v0.x * inv, v0.y * inv, v0.z * inv, v0.w * inv);
        if (tid < 68)
            s_sm4[tid + 128] = make_float4(v1.x * inv, v1.y * inv, v1.z * inv, v1.w * inv);
        if (tid >= 68 && tid < 130)                            // float4 idx 196..257
            s_sm4[tid + 128] = make_float4(0.f, 0.f, 0.f, 0.f);
    }
    __syncthreads();

    // ---- register window: w[0..15] = s[8t .. 8t+16) ----
    float w[16];
    #pragma unroll
    for (int q = 0; q < 4; q++) {
        const float4 a = *reinterpret_cast<const float4*>(&s_sm[8 * tid + 4 * q]);
        w[4*q+0] = a.x; w[4*q+1] = a.y; w[4*q+2] = a.z; w[4*q+3] = a.w;
    }

    const int i0   = blockIdx.x * ROWS_PER_CTA;
    const int iend = i0 + ROWS_PER_CTA;                        // exact: no clamp

    for (int i = i0; i < iend; ++i) {
        const float si = s_sm[i];                              // broadcast LDS
        float* rowp    = out + (size_t)b * DIMSQ + (size_t)i * DIM;
        const int A8   = (-(b + i)) & 7;

        // head scalars j in [0, A8)
        if (tid < A8) rowp[tid] = si * s_sm[tid];

        // per-phase: NQ octets + zero tail (tail j >= 994 > FEAT)
        #define CASE(K)                                                            \
            {                                                                      \
                constexpr int NQ = ((K) <= 1) ? 125 : 124;                         \
                constexpr int TS = (K) + 8 * NQ;        /* tail start */           \
                if (tid < NQ) {                                                    \
                    float* dst = rowp + (K) + 8 * tid;  /* 32B-aligned */          \
                    STG256(dst, si*w[(K)+0], si*w[(K)+1], si*w[(K)+2],             \
                                si*w[(K)+3], si*w[(K)+4], si*w[(K)+5],             \
                                si*w[(K)+6], si*w[(K)+7]);                         \
                }                                                                  \
                if (TS < DIM && tid >= 120 && tid < 120 + (DIM - TS))              \
                    rowp[TS + (tid - 120)] = 0.0f;                                 \
            }
        switch (A8) {
            case 0: CASE(0); break;
            case 1: CASE(1); break;
            case 2: CASE(2); break;
            case 3: CASE(3); break;
            case 4: CASE(4); break;
            case 5: CASE(5); break;
            case 6: CASE(6); break;
            default: CASE(7); break;
        }
        #undef CASE
    }
}

extern "C" void kernel_launch(void* const* d_in, const int* in_sizes, int n_in,
                              void* d_out, int out_size) {
    const float* x   = (const float*)d_in[0];
    float*       out = (float*)d_out;
    amp_kernel<<<dim3(CTAS_X, BATCH), 128>>>(x, out);
}